// round 13
// baseline (speedup 1.0000x reference)
#include <cuda_runtime.h>
#include <cuda_bf16.h>
#include <cstdint>
#include <cstddef>

// ---------------- problem constants ----------------
constexpr int Bc = 16;
constexpr int Nc = 128;
constexpr int Mc = 1024;
constexpr int DNc = 512;
constexpr int DEc = 256;
constexpr int WNc = 128;
constexpr int WEc = 128;
constexpr int Pc = 512;
constexpr int HIDc = 256;
constexpr int CI = 512;        // 2*(WN+WE)
constexpr int HID3 = 3 * HIDc; // 768

// ---------------- scratch (device global, no allocs) ----------------
constexpr size_t OFF_XM    = 0;
constexpr size_t OFF_XWCAT = OFF_XM    + (size_t)Bc*Nc*DNc;
constexpr size_t OFF_H     = OFF_XWCAT + (size_t)Bc*Nc*256;
constexpr size_t OFF_EG    = OFF_H     + (size_t)Bc*Nc*WNc;
constexpr size_t OFF_EGWE  = OFF_EG    + (size_t)Bc*Mc*DEc;
constexpr size_t OFF_G     = OFF_EGWE  + (size_t)Bc*Mc*WEc;
constexpr size_t OFF_PAIRE = OFF_G     + (size_t)Bc*Mc*WEc;
constexpr size_t OFF_CI    = OFF_PAIRE + (size_t)Bc*Pc*DEc;
constexpr size_t OFF_HID   = OFF_CI    + (size_t)Bc*Pc*CI;
constexpr size_t OFF_WNCAT = OFF_HID   + (size_t)Bc*Pc*HID3;   // 512x256
constexpr size_t OFF_WCAT  = OFF_WNCAT + (size_t)DNc*256;      // 512x768
constexpr size_t OFF_BCAT  = OFF_WCAT  + (size_t)CI*HID3;      // 768
constexpr size_t OFF_WER   = OFF_BCAT  + HID3;                 // 256x128
constexpr size_t OFF_WE2R  = OFF_WER   + (size_t)DEc*WEc;      // 256x128
constexpr size_t SCRATCH_TOTAL = OFF_WE2R + (size_t)DEc*WEc;

__device__ float d_scratch[SCRATCH_TOTAL];

// CSR for scatter-add: per-batch src-node -> ascending edge list
__device__ int d_csr_off[Bc][Nc + 1];
__device__ int d_csr_list[Bc][Mc];

// ---------------- tf32 / cp.async helpers ----------------
__device__ __forceinline__ uint32_t f2tf32(float f) {
    uint32_t u;
    asm("cvt.rna.tf32.f32 %0, %1;" : "=r"(u) : "f"(f));
    return u;
}
__device__ __forceinline__ float rtf(float f) {
    return __uint_as_float(f2tf32(f));
}
__device__ __forceinline__ void mma_tf32(float c[4], const uint32_t a[4], const uint32_t b[2]) {
    asm volatile(
        "mma.sync.aligned.m16n8k8.row.col.f32.tf32.tf32.f32 "
        "{%0,%1,%2,%3}, {%4,%5,%6,%7}, {%8,%9}, {%0,%1,%2,%3};"
        : "+f"(c[0]), "+f"(c[1]), "+f"(c[2]), "+f"(c[3])
        : "r"(a[0]), "r"(a[1]), "r"(a[2]), "r"(a[3]), "r"(b[0]), "r"(b[1]));
}
__device__ __forceinline__ void cp16(void* s, const void* g) {
    uint32_t sa = (uint32_t)__cvta_generic_to_shared(s);
    asm volatile("cp.async.cg.shared.global [%0], [%1], 16;" :: "r"(sa), "l"(g));
}

// ---------------- pipelined tf32 GEMM device function ----------------
// Operands A and W MUST already be tf32-rounded (bits fed raw to mma).
constexpr int AS_STR = 20;
constexpr int BS_STR = 136;

struct SmemGemm {
    float As[2][128][AS_STR];
    float Bs[2][16][BS_STR];
};  // 37,888 bytes

template<int EPI, bool RND>  // EPI: 0 none, 1 relu, 3 bias+relu; RND: tf32-round output
__device__ __forceinline__ void gemm_dev(SmemGemm& S,
    const float* __restrict__ A, const float* __restrict__ W, float* __restrict__ C,
    int K, int Ncols, int ldc, int rowBlk, int colBlk, const float* __restrict__ bias)
{
    const int tid  = threadIdx.x;
    const int wid  = tid >> 5, lane = tid & 31;
    const int wr   = wid >> 1, wc = wid & 1;
    const int g    = lane >> 2, tig = lane & 3;
    const int wrBase = wr * 32, wcBase = wc * 64;

    const int a_row = tid >> 2;
    const int a_c4  = (tid & 3) * 4;
    const int b_row = tid >> 5;
    const int b_c4  = (tid & 31) * 4;

    float acc[2][8][4];
    #pragma unroll
    for (int mt = 0; mt < 2; mt++)
        #pragma unroll
        for (int nt = 0; nt < 8; nt++)
            #pragma unroll
            for (int q = 0; q < 4; q++) acc[mt][nt][q] = 0.f;

    const int KT = K >> 4;

    {
        cp16(&S.As[0][a_row][a_c4],      A + (size_t)(rowBlk + a_row) * K + a_c4);
        cp16(&S.As[0][a_row + 64][a_c4], A + (size_t)(rowBlk + a_row + 64) * K + a_c4);
        cp16(&S.Bs[0][b_row][b_c4],      W + (size_t)b_row * Ncols + colBlk + b_c4);
        cp16(&S.Bs[0][b_row + 8][b_c4],  W + (size_t)(b_row + 8) * Ncols + colBlk + b_c4);
        asm volatile("cp.async.commit_group;");
    }

    for (int kt = 0; kt < KT; kt++) {
        const int cur = kt & 1;
        if (kt + 1 < KT) {
            const int nxt = cur ^ 1;
            const int k0 = (kt + 1) << 4;
            cp16(&S.As[nxt][a_row][a_c4],      A + (size_t)(rowBlk + a_row) * K + k0 + a_c4);
            cp16(&S.As[nxt][a_row + 64][a_c4], A + (size_t)(rowBlk + a_row + 64) * K + k0 + a_c4);
            cp16(&S.Bs[nxt][b_row][b_c4],      W + (size_t)(k0 + b_row) * Ncols + colBlk + b_c4);
            cp16(&S.Bs[nxt][b_row + 8][b_c4],  W + (size_t)(k0 + b_row + 8) * Ncols + colBlk + b_c4);
            asm volatile("cp.async.commit_group;");
            asm volatile("cp.async.wait_group 1;");
        } else {
            asm volatile("cp.async.wait_group 0;");
        }
        __syncthreads();

        #pragma unroll
        for (int ks = 0; ks < 2; ks++) {
            const int kb = ks * 8;
            uint32_t afr[2][4];
            #pragma unroll
            for (int mt = 0; mt < 2; mt++) {
                int rb = wrBase + mt * 16;
                afr[mt][0] = __float_as_uint(S.As[cur][rb + g    ][kb + tig]);
                afr[mt][1] = __float_as_uint(S.As[cur][rb + g + 8][kb + tig]);
                afr[mt][2] = __float_as_uint(S.As[cur][rb + g    ][kb + tig + 4]);
                afr[mt][3] = __float_as_uint(S.As[cur][rb + g + 8][kb + tig + 4]);
            }
            #pragma unroll
            for (int nt = 0; nt < 8; nt++) {
                uint32_t bfr[2];
                int col = wcBase + nt * 8 + g;
                bfr[0] = __float_as_uint(S.Bs[cur][kb + tig    ][col]);
                bfr[1] = __float_as_uint(S.Bs[cur][kb + tig + 4][col]);
                mma_tf32(acc[0][nt], afr[0], bfr);
                mma_tf32(acc[1][nt], afr[1], bfr);
            }
        }
        __syncthreads();
    }

    #pragma unroll
    for (int mt = 0; mt < 2; mt++) {
        int r0 = rowBlk + wrBase + mt * 16 + g;
        int r1 = r0 + 8;
        #pragma unroll
        for (int nt = 0; nt < 8; nt++) {
            int c0 = colBlk + wcBase + nt * 8 + tig * 2;
            float v0 = acc[mt][nt][0], v1 = acc[mt][nt][1];
            float v2 = acc[mt][nt][2], v3 = acc[mt][nt][3];
            if (EPI == 3) {
                float b0 = bias[c0], b1 = bias[c0 + 1];
                v0 += b0; v1 += b1; v2 += b0; v3 += b1;
            }
            if (EPI == 1 || EPI == 3) {
                v0 = fmaxf(v0, 0.f); v1 = fmaxf(v1, 0.f);
                v2 = fmaxf(v2, 0.f); v3 = fmaxf(v3, 0.f);
            }
            if (RND) { v0 = rtf(v0); v1 = rtf(v1); v2 = rtf(v2); v3 = rtf(v3); }
            *(float2*)(C + (size_t)r0 * ldc + c0) = make_float2(v0, v1);
            *(float2*)(C + (size_t)r1 * ldc + c0) = make_float2(v2, v3);
        }
    }
}

// ---------------- branch GEMM kernels ----------------
__global__ void __launch_bounds__(256) k_gemm_node(
    const float* __restrict__ Xm, const float* __restrict__ Wncat, float* __restrict__ XWcat)
{
    __shared__ SmemGemm S;
    int id = blockIdx.x;  // 32
    gemm_dev<0,false>(S, Xm, Wncat, XWcat, 512, 256, 256, (id >> 1) * 128, (id & 1) * 128, nullptr);
}

__global__ void __launch_bounds__(256) k_gemm_edge(
    const float* __restrict__ Eg, const float* __restrict__ WeR, float* __restrict__ EgWe)
{
    __shared__ SmemGemm S;
    gemm_dev<0,false>(S, Eg, WeR, EgWe, 256, 128, 128, blockIdx.x * 128, 0, nullptr);
}

__global__ void __launch_bounds__(256) k_gemm_pair(
    const float* __restrict__ pairE, const float* __restrict__ We2R, float* __restrict__ ci)
{
    __shared__ SmemGemm S;
    // relu(pairE @ We2), tf32-rounded, written straight into ci[:, 384:512]
    gemm_dev<1,true>(S, pairE, We2R, ci + 384, 256, 128, CI, blockIdx.x * 128, 0, nullptr);
}

__global__ void __launch_bounds__(256) k_gemm_heads(
    const float* __restrict__ ci, const float* __restrict__ Wcat,
    const float* __restrict__ bcat, float* __restrict__ hid)
{
    __shared__ SmemGemm S;
    int id = blockIdx.x;  // 384
    gemm_dev<3,false>(S, ci, Wcat, hid, 512, 768, 768, (id / 6) * 128, (id % 6) * 128, bcat);
}

// ---------------- prep kernels (per branch) ----------------
// EDGE branch: Eg gather [0,16384) + WeR [16384,16448) + CSR [16448,16464)
constexpr int PE_EG_END  = Bc * Mc;                        // 16384
constexpr int PE_WE_END  = PE_EG_END + (DEc * WEc) / 512;  // +64
constexpr int PE_TOTAL   = PE_WE_END + Bc;                 // +16

__global__ void __launch_bounds__(128) k_prep_edge(
    const float* __restrict__ ef, const int* __restrict__ eidx, const int* __restrict__ nedg,
    float* __restrict__ Eg, const float* __restrict__ We, float* __restrict__ WeR)
{
    const int blk = blockIdx.x, tid = threadIdx.x;
    if (blk < PE_EG_END) {
        int b = blk >> 10, m = blk & 1023;
        float2 v = make_float2(0.f, 0.f);
        if (m < nedg[b]) {
            int s = eidx[b * 2 * Mc + m];
            int d = eidx[b * 2 * Mc + Mc + m];
            v = ((const float2*)(ef + (((size_t)b * Nc + s) * Nc + d) * DEc))[tid];
            v.x = rtf(v.x); v.y = rtf(v.y);
        }
        ((float2*)(Eg + (size_t)blk * DEc))[tid] = v;
    } else if (blk < PE_WE_END) {
        int idx = (blk - PE_EG_END) * 128 + tid;
        float4 v = ((const float4*)We)[idx];
        v.x = rtf(v.x); v.y = rtf(v.y); v.z = rtf(v.z); v.w = rtf(v.w);
        ((float4*)WeR)[idx] = v;
    } else {
        __shared__ int ssrc[Mc];
        __shared__ int scnt[128];
        int b = blk - PE_WE_END;
        for (int i = tid; i < Mc; i += 128) ssrc[i] = eidx[b * 2 * Mc + i];
        __syncthreads();
        int cnt = 0;
        for (int m = 0; m < Mc; m++) if (ssrc[m] == tid) cnt++;
        scnt[tid] = cnt;
        __syncthreads();
        int off = 0;
        for (int u = 0; u < tid; u++) off += scnt[u];
        d_csr_off[b][tid] = off;
        if (tid == 127) d_csr_off[b][128] = off + cnt;
        int c = off;
        for (int m = 0; m < Mc; m++)
            if (ssrc[m] == tid) d_csr_list[b][c++] = m;
    }
}

// NODE branch: Xm [0,2048) + Wncat [2048,2560) + Wcat/bcat [2560,3584)
constexpr int PN_XM_END = Bc * Nc;                       // 2048
constexpr int PN_WN_END = PN_XM_END + (DNc * WNc) / 128; // +512
constexpr int PN_TOTAL  = PN_WN_END + (CI * HIDc) / 128; // +1024

__global__ void __launch_bounds__(128) k_prep_node(
    const float* __restrict__ nf, const int* __restrict__ nobj, float* __restrict__ Xm,
    const float* __restrict__ Wn, const float* __restrict__ Wn2, float* __restrict__ Wncat,
    const float* __restrict__ lrW1, const float* __restrict__ scrW1, const float* __restrict__ mrW1,
    const float* __restrict__ lrb1, const float* __restrict__ scrb1, const float* __restrict__ mrb1,
    float* __restrict__ Wcat, float* __restrict__ bcat)
{
    const int blk = blockIdx.x, tid = threadIdx.x;
    if (blk < PN_XM_END) {
        int b = blk >> 7, n = blk & 127;
        float4 v = make_float4(0.f, 0.f, 0.f, 0.f);
        if (n < nobj[b]) {
            v = ((const float4*)(nf + (size_t)blk * DNc))[tid];
            v.x = rtf(v.x); v.y = rtf(v.y); v.z = rtf(v.z); v.w = rtf(v.w);
        }
        ((float4*)(Xm + (size_t)blk * DNc))[tid] = v;
    } else if (blk < PN_WN_END) {
        int idx = (blk - PN_XM_END) * 128 + tid;
        int k = idx >> 7, c = idx & 127;
        Wncat[(size_t)k * 256 + c]       = rtf(Wn[idx]);
        Wncat[(size_t)k * 256 + 128 + c] = rtf(Wn2[idx]);
    } else {
        int idx = (blk - PN_WN_END) * 128 + tid;
        int k = idx >> 8, c = idx & 255;
        Wcat[(size_t)k * HID3 + c]             = rtf(lrW1[idx]);
        Wcat[(size_t)k * HID3 + HIDc + c]      = rtf(scrW1[idx]);
        Wcat[(size_t)k * HID3 + 2 * HIDc + c]  = rtf(mrW1[idx]);
        if (blk == PN_WN_END) {
            for (int i = tid; i < HIDc; i += 128) {
                bcat[i]             = lrb1[i];
                bcat[HIDc + i]      = scrb1[i];
                bcat[2 * HIDc + i]  = mrb1[i];
            }
        }
    }
}

// PAIR branch: pairE [0,8192) + We2R [8192,8256)
constexpr int PP_PAIR_END = Bc * Pc;                         // 8192
constexpr int PP_TOTAL    = PP_PAIR_END + (DEc * WEc) / 512; // +64

__global__ void __launch_bounds__(128) k_prep_pair(
    const float* __restrict__ ef, const int* __restrict__ opair, float* __restrict__ pairE,
    const float* __restrict__ We2, float* __restrict__ We2R)
{
    const int blk = blockIdx.x, tid = threadIdx.x;
    if (blk < PP_PAIR_END) {
        int b = blk >> 9, k = blk & 511;
        int p0 = opair[(b * Pc + k) * 2 + 0];
        int p1 = opair[(b * Pc + k) * 2 + 1];
        float2 v = ((const float2*)(ef + (((size_t)b * Nc + p0) * Nc + p1) * DEc))[tid];
        v.x = rtf(v.x); v.y = rtf(v.y);
        ((float2*)(pairE + (size_t)blk * DEc))[tid] = v;
    } else {
        int idx = (blk - PP_PAIR_END) * 128 + tid;
        float4 v = ((const float4*)We2)[idx];
        v.x = rtf(v.x); v.y = rtf(v.y); v.z = rtf(v.z); v.w = rtf(v.w);
        ((float4*)We2R)[idx] = v;
    }
}

// ---------------- sparse adjacency (shared device fn; loops trimmed to cnt) --------
__device__ __forceinline__ void adj_dev(
    const float* __restrict__ Adj, const float* __restrict__ Feat,
    const int* __restrict__ cntArr, float* __restrict__ Out,
    int blk, int ROWLEN, int featStride,
    float* srow, int* sidx, float* sval, int* scount)
{
    const int b   = blk / ROWLEN;
    const int i   = blk % ROWLEN;
    const int tid = threadIdx.x;
    const int cnt = cntArr[b];

    float* outRow = Out + (size_t)blk * 128;
    if (i >= cnt) { outRow[tid] = 0.f; return; }

    // stage only the live prefix of the row (j < cnt matters; rest predicated off)
    const float4* A4 = (const float4*)(Adj + ((size_t)b * ROWLEN + i) * ROWLEN);
    float4* s4 = (float4*)srow;
    const int nv4 = (cnt + 3) >> 2;
    for (int j = tid; j < nv4; j += 128) s4[j] = A4[j];
    __syncthreads();

    if (tid < 32) {
        int cn = 0;
        for (int base = 0; base < cnt; base += 32) {
            int j = base + tid;
            float v = (j < cnt) ? srow[j] : 0.f;
            bool nz = (v != 0.f) && (j < cnt);
            unsigned msk = __ballot_sync(0xffffffffu, nz);
            int pos = cn + __popc(msk & ((1u << tid) - 1u));
            if (nz) { sidx[pos] = j; sval[pos] = v; }
            cn += __popc(msk);
        }
        if (tid == 0) *scount = cn;
    }
    __syncthreads();

    const int n = *scount;
    const float* Fb = Feat + (size_t)b * ROWLEN * featStride;
    float acc = Fb[(size_t)i * featStride + tid];     // + eye*mask term
    for (int t = 0; t < n; t++)
        acc = fmaf(sval[t], Fb[(size_t)sidx[t] * featStride + tid], acc);
    outRow[tid] = fmaxf(acc, 0.f);
}

__global__ void __launch_bounds__(128) k_adj_node(
    const float* __restrict__ adjN, const float* __restrict__ XWcat,
    const int* __restrict__ nobj, float* __restrict__ h)
{
    __shared__ float srow[Nc];
    __shared__ int   sidx[Nc];
    __shared__ float sval[Nc];
    __shared__ int   scount;
    adj_dev(adjN, XWcat, nobj, h, blockIdx.x, Nc, 256, srow, sidx, sval, &scount);
}

__global__ void __launch_bounds__(128) k_adj_edge(
    const float* __restrict__ adjM, const float* __restrict__ EgWe,
    const int* __restrict__ nedg, float* __restrict__ g)
{
    __shared__ float srow[Mc];
    __shared__ int   sidx[Mc];
    __shared__ float sval[Mc];
    __shared__ int   scount;
    adj_dev(adjM, EgWe, nedg, g, blockIdx.x, Mc, 128, srow, sidx, sval, &scount);
}

// ---------------- build classifier input (cols 0..384; agg inlined via CSR) -------
__global__ void __launch_bounds__(128) k_build_ci(
    const int* __restrict__ opair, const int* __restrict__ nobj,
    const float* __restrict__ h, const float* __restrict__ g,
    const float* __restrict__ XWcat, float* __restrict__ ci)
{
    int bk = blockIdx.x;
    int b = bk >> 9, k = bk & 511;
    int p0 = opair[(b * Pc + k) * 2 + 0];
    int p1 = opair[(b * Pc + k) * 2 + 1];
    int no = nobj[b];
    float nm0 = (p0 < no) ? 1.f : 0.f;
    float nm1 = (p1 < no) ? 1.f : 0.f;
    int c = threadIdx.x;
    const float* hb = h    + (size_t)b * Nc * WNc;
    const float* gb = g    + (size_t)b * Mc * WEc;
    const float* xb = XWcat + (size_t)b * Nc * 256 + 128;   // Xp = cols [128,256)
    float* co = ci + (size_t)bk * CI;

    // agg rows for p0/p1 computed inline (same ascending-edge order as before)
    float a0 = 0.f, a1 = 0.f;
    {
        int off = d_csr_off[b][p0], end = d_csr_off[b][p0 + 1];
        for (int t = off; t < end; t++)
            a0 += gb[(size_t)d_csr_list[b][t] * WEc + c];
    }
    {
        int off = d_csr_off[b][p1], end = d_csr_off[b][p1 + 1];
        for (int t = off; t < end; t++)
            a1 += gb[(size_t)d_csr_list[b][t] * WEc + c];
    }

    co[c]       = rtf(hb[(size_t)p0 * WNc + c] + hb[(size_t)p1 * WNc + c]);
    co[128 + c] = rtf(a0 * nm0 + a1 * nm1);
    co[256 + c] = rtf(fmaxf(xb[(size_t)p0 * 256 + c] + xb[(size_t)p1 * 256 + c], 0.f));
}

// ---------------- fused output layers (lr 9 | cr 6 | mr 17) ----------------
__global__ void __launch_bounds__(128) k_heads_out(
    const float* __restrict__ hid,
    const float* __restrict__ lrW2,  const float* __restrict__ lrb2,
    const float* __restrict__ scrW2, const float* __restrict__ scrb2,
    const float* __restrict__ mrW2,  const float* __restrict__ mrb2,
    float* __restrict__ out)
{
    __shared__ float sh[HID3];
    const int row = blockIdx.x, tid = threadIdx.x;
    const float2* hr2 = (const float2*)(hid + (size_t)row * HID3);
    float2* sh2 = (float2*)sh;
    #pragma unroll
    for (int i = 0; i < 3; i++) sh2[i * 128 + tid] = hr2[i * 128 + tid];
    __syncthreads();

    const int o    = tid >> 2;
    const int part = tid & 3;
    const float* W2; const float* b2; int off, OUT, oo; float* dst;
    const size_t rows = (size_t)Bc * Pc;
    if (o < 9)       { W2 = lrW2;  b2 = lrb2;  off = 0;   OUT = 9;  oo = o;      dst = out; }
    else if (o < 15) { W2 = scrW2; b2 = scrb2; off = 256; OUT = 6;  oo = o - 9;  dst = out + rows * 9; }
    else             { W2 = mrW2;  b2 = mrb2;  off = 512; OUT = 17; oo = o - 15; dst = out + rows * 15; }

    float acc = 0.f;
    const int k0 = part * 64;
    #pragma unroll 4
    for (int kk = k0; kk < k0 + 64; kk++)
        acc += sh[off + kk] * W2[kk * OUT + oo];
    acc += __shfl_xor_sync(0xffffffffu, acc, 1);
    acc += __shfl_xor_sync(0xffffffffu, acc, 2);
    if (part == 0) dst[(size_t)row * OUT + oo] = acc + b2[oo];
}

// ---------------- launch (3 parallel stream branches, fork/join) ----------------
extern "C" void kernel_launch(void* const* d_in, const int* in_sizes, int n_in,
                              void* d_out, int out_size)
{
    const float* nf    = (const float*)d_in[0];
    const float* ef    = (const float*)d_in[1];
    const float* adj   = (const float*)d_in[2];
    const float* ladj  = (const float*)d_in[3];
    const int*   eidx  = (const int*)d_in[4];
    const int*   opair = (const int*)d_in[5];
    const int*   nobj  = (const int*)d_in[6];
    const int*   nedg  = (const int*)d_in[7];
    const float* Wn    = (const float*)d_in[8];
    const float* We    = (const float*)d_in[9];
    const float* Wn2   = (const float*)d_in[10];
    const float* We2   = (const float*)d_in[11];
    const float* scrW1 = (const float*)d_in[12];
    const float* scrb1 = (const float*)d_in[13];
    const float* scrW2 = (const float*)d_in[14];
    const float* scrb2 = (const float*)d_in[15];
    const float* lrW1  = (const float*)d_in[16];
    const float* lrb1  = (const float*)d_in[17];
    const float* lrW2  = (const float*)d_in[18];
    const float* lrb2  = (const float*)d_in[19];
    const float* mrW1  = (const float*)d_in[20];
    const float* mrb1  = (const float*)d_in[21];
    const float* mrW2  = (const float*)d_in[22];
    const float* mrb2  = (const float*)d_in[23];
    float* out = (float*)d_out;

    float* S = nullptr;
    cudaGetSymbolAddress((void**)&S, d_scratch);
    float* Xm    = S + OFF_XM;
    float* XWcat = S + OFF_XWCAT;
    float* h     = S + OFF_H;
    float* Eg    = S + OFF_EG;
    float* EgWe  = S + OFF_EGWE;
    float* g     = S + OFF_G;
    float* pairE = S + OFF_PAIRE;
    float* ci    = S + OFF_CI;
    float* hid   = S + OFF_HID;
    float* Wncat = S + OFF_WNCAT;
    float* Wcat  = S + OFF_WCAT;
    float* bcat  = S + OFF_BCAT;
    float* WeR   = S + OFF_WER;
    float* We2R  = S + OFF_WE2R;

    cudaStream_t s1, s2;
    cudaStreamCreateWithFlags(&s1, cudaStreamNonBlocking);
    cudaStreamCreateWithFlags(&s2, cudaStreamNonBlocking);
    cudaEvent_t eF, eN, eP;
    cudaEventCreateWithFlags(&eF, cudaEventDisableTiming);
    cudaEventCreateWithFlags(&eN, cudaEventDisableTiming);
    cudaEventCreateWithFlags(&eP, cudaEventDisableTiming);

    // fork
    cudaEventRecord(eF, 0);
    cudaStreamWaitEvent(s1, eF, 0);
    cudaStreamWaitEvent(s2, eF, 0);

    // NODE branch (s1): Xm mask + weight packs -> X@[Wn|Wn2] -> node adjacency
    k_prep_node<<<PN_TOTAL, 128, 0, s1>>>(nf, nobj, Xm, Wn, Wn2, Wncat,
                                          lrW1, scrW1, mrW1, lrb1, scrb1, mrb1, Wcat, bcat);
    k_gemm_node<<<32, 256, 0, s1>>>(Xm, Wncat, XWcat);
    k_adj_node<<<Bc * Nc, 128, 0, s1>>>(adj, XWcat, nobj, h);
    cudaEventRecord(eN, s1);

    // PAIR branch (s2): pairE gather -> relu(pairE@We2) -> ci[:,384:]
    k_prep_pair<<<PP_TOTAL, 128, 0, s2>>>(ef, opair, pairE, We2, We2R);
    k_gemm_pair<<<64, 256, 0, s2>>>(pairE, We2R, ci);
    cudaEventRecord(eP, s2);

    // EDGE branch (origin): Eg gather + CSR -> Eg@We -> line adjacency
    k_prep_edge<<<PE_TOTAL, 128>>>(ef, eidx, nedg, Eg, We, WeR);
    k_gemm_edge<<<128, 256>>>(Eg, WeR, EgWe);
    k_adj_edge<<<Bc * Mc, 128>>>(ladj, EgWe, nedg, g);

    // join
    cudaStreamWaitEvent(0, eN, 0);
    cudaStreamWaitEvent(0, eP, 0);

    // tail: ci cols 0..384 (agg inlined), heads GEMM, output layers
    k_build_ci<<<Bc * Pc, 128>>>(opair, nobj, h, g, XWcat, ci);
    k_gemm_heads<<<(Bc * Pc / 128) * 6, 256>>>(ci, Wcat, bcat, hid);
    k_heads_out<<<Bc * Pc, 128>>>(hid, lrW2, lrb2, scrW2, scrb2, mrW2, mrb2, out);

    cudaEventDestroy(eF);
    cudaEventDestroy(eN);
    cudaEventDestroy(eP);
    cudaStreamDestroy(s1);
    cudaStreamDestroy(s2);
}

// round 15
// speedup vs baseline: 1.0477x; 1.0477x over previous
#include <cuda_runtime.h>
#include <cuda_bf16.h>
#include <cstdint>
#include <cstddef>

// ---------------- problem constants ----------------
constexpr int Bc = 16;
constexpr int Nc = 128;
constexpr int Mc = 1024;
constexpr int DNc = 512;
constexpr int DEc = 256;
constexpr int WNc = 128;
constexpr int WEc = 128;
constexpr int Pc = 512;
constexpr int HIDc = 256;
constexpr int CI = 512;        // 2*(WN+WE)
constexpr int HID3 = 3 * HIDc; // 768

// ---------------- scratch (device global, no allocs) ----------------
constexpr size_t OFF_XM    = 0;
constexpr size_t OFF_XWCAT = OFF_XM    + (size_t)Bc*Nc*DNc;
constexpr size_t OFF_H     = OFF_XWCAT + (size_t)Bc*Nc*256;
constexpr size_t OFF_EG    = OFF_H     + (size_t)Bc*Nc*WNc;
constexpr size_t OFF_EGWE  = OFF_EG    + (size_t)Bc*Mc*DEc;
constexpr size_t OFF_G     = OFF_EGWE  + (size_t)Bc*Mc*WEc;
constexpr size_t OFF_AGG   = OFF_G     + (size_t)Bc*Mc*WEc;
constexpr size_t OFF_PAIRE = OFF_AGG   + (size_t)Bc*Nc*WEc;
constexpr size_t OFF_CI    = OFF_PAIRE + (size_t)Bc*Pc*DEc;
constexpr size_t OFF_HID   = OFF_CI    + (size_t)Bc*Pc*CI;
constexpr size_t OFF_WNCAT = OFF_HID   + (size_t)Bc*Pc*HID3;   // 512x256
constexpr size_t OFF_WCAT  = OFF_WNCAT + (size_t)DNc*256;      // 512x768
constexpr size_t OFF_BCAT  = OFF_WCAT  + (size_t)CI*HID3;      // 768
constexpr size_t OFF_WER   = OFF_BCAT  + HID3;                 // 256x128
constexpr size_t OFF_WE2R  = OFF_WER   + (size_t)DEc*WEc;      // 256x128
constexpr size_t SCRATCH_TOTAL = OFF_WE2R + (size_t)DEc*WEc;

__device__ float d_scratch[SCRATCH_TOTAL];

// CSR for scatter-add: per-batch src-node -> ascending edge list
__device__ int d_csr_off[Bc][Nc + 1];
__device__ int d_csr_list[Bc][Mc];

// ---------------- tf32 / cp.async helpers ----------------
__device__ __forceinline__ uint32_t f2tf32(float f) {
    uint32_t u;
    asm("cvt.rna.tf32.f32 %0, %1;" : "=r"(u) : "f"(f));
    return u;
}
__device__ __forceinline__ float rtf(float f) {
    return __uint_as_float(f2tf32(f));
}
__device__ __forceinline__ void mma_tf32(float c[4], const uint32_t a[4], const uint32_t b[2]) {
    asm volatile(
        "mma.sync.aligned.m16n8k8.row.col.f32.tf32.tf32.f32 "
        "{%0,%1,%2,%3}, {%4,%5,%6,%7}, {%8,%9}, {%0,%1,%2,%3};"
        : "+f"(c[0]), "+f"(c[1]), "+f"(c[2]), "+f"(c[3])
        : "r"(a[0]), "r"(a[1]), "r"(a[2]), "r"(a[3]), "r"(b[0]), "r"(b[1]));
}
__device__ __forceinline__ void cp16(void* s, const void* g) {
    uint32_t sa = (uint32_t)__cvta_generic_to_shared(s);
    asm volatile("cp.async.cg.shared.global [%0], [%1], 16;" :: "r"(sa), "l"(g));
}

// ---------------- pipelined tf32 GEMM device function ----------------
// Operands A and W MUST already be tf32-rounded (bits fed raw to mma).
constexpr int AS_STR = 20;
constexpr int BS_STR = 136;

struct SmemGemm {
    float As[2][128][AS_STR];
    float Bs[2][16][BS_STR];
};  // 37,888 bytes

template<int EPI, bool RND>  // EPI: 0 none, 1 relu, 3 bias+relu; RND: tf32-round output
__device__ __forceinline__ void gemm_dev(SmemGemm& S,
    const float* __restrict__ A, const float* __restrict__ W, float* __restrict__ C,
    int K, int Ncols, int ldc, int rowBlk, int colBlk, const float* __restrict__ bias)
{
    const int tid  = threadIdx.x;
    const int wid  = tid >> 5, lane = tid & 31;
    const int wr   = wid >> 1, wc = wid & 1;
    const int g    = lane >> 2, tig = lane & 3;
    const int wrBase = wr * 32, wcBase = wc * 64;

    const int a_row = tid >> 2;
    const int a_c4  = (tid & 3) * 4;
    const int b_row = tid >> 5;
    const int b_c4  = (tid & 31) * 4;

    float acc[2][8][4];
    #pragma unroll
    for (int mt = 0; mt < 2; mt++)
        #pragma unroll
        for (int nt = 0; nt < 8; nt++)
            #pragma unroll
            for (int q = 0; q < 4; q++) acc[mt][nt][q] = 0.f;

    const int KT = K >> 4;

    {
        cp16(&S.As[0][a_row][a_c4],      A + (size_t)(rowBlk + a_row) * K + a_c4);
        cp16(&S.As[0][a_row + 64][a_c4], A + (size_t)(rowBlk + a_row + 64) * K + a_c4);
        cp16(&S.Bs[0][b_row][b_c4],      W + (size_t)b_row * Ncols + colBlk + b_c4);
        cp16(&S.Bs[0][b_row + 8][b_c4],  W + (size_t)(b_row + 8) * Ncols + colBlk + b_c4);
        asm volatile("cp.async.commit_group;");
    }

    for (int kt = 0; kt < KT; kt++) {
        const int cur = kt & 1;
        if (kt + 1 < KT) {
            const int nxt = cur ^ 1;
            const int k0 = (kt + 1) << 4;
            cp16(&S.As[nxt][a_row][a_c4],      A + (size_t)(rowBlk + a_row) * K + k0 + a_c4);
            cp16(&S.As[nxt][a_row + 64][a_c4], A + (size_t)(rowBlk + a_row + 64) * K + k0 + a_c4);
            cp16(&S.Bs[nxt][b_row][b_c4],      W + (size_t)(k0 + b_row) * Ncols + colBlk + b_c4);
            cp16(&S.Bs[nxt][b_row + 8][b_c4],  W + (size_t)(k0 + b_row + 8) * Ncols + colBlk + b_c4);
            asm volatile("cp.async.commit_group;");
            asm volatile("cp.async.wait_group 1;");
        } else {
            asm volatile("cp.async.wait_group 0;");
        }
        __syncthreads();

        #pragma unroll
        for (int ks = 0; ks < 2; ks++) {
            const int kb = ks * 8;
            uint32_t afr[2][4];
            #pragma unroll
            for (int mt = 0; mt < 2; mt++) {
                int rb = wrBase + mt * 16;
                afr[mt][0] = __float_as_uint(S.As[cur][rb + g    ][kb + tig]);
                afr[mt][1] = __float_as_uint(S.As[cur][rb + g + 8][kb + tig]);
                afr[mt][2] = __float_as_uint(S.As[cur][rb + g    ][kb + tig + 4]);
                afr[mt][3] = __float_as_uint(S.As[cur][rb + g + 8][kb + tig + 4]);
            }
            #pragma unroll
            for (int nt = 0; nt < 8; nt++) {
                uint32_t bfr[2];
                int col = wcBase + nt * 8 + g;
                bfr[0] = __float_as_uint(S.Bs[cur][kb + tig    ][col]);
                bfr[1] = __float_as_uint(S.Bs[cur][kb + tig + 4][col]);
                mma_tf32(acc[0][nt], afr[0], bfr);
                mma_tf32(acc[1][nt], afr[1], bfr);
            }
        }
        __syncthreads();
    }

    #pragma unroll
    for (int mt = 0; mt < 2; mt++) {
        int r0 = rowBlk + wrBase + mt * 16 + g;
        int r1 = r0 + 8;
        #pragma unroll
        for (int nt = 0; nt < 8; nt++) {
            int c0 = colBlk + wcBase + nt * 8 + tig * 2;
            float v0 = acc[mt][nt][0], v1 = acc[mt][nt][1];
            float v2 = acc[mt][nt][2], v3 = acc[mt][nt][3];
            if (EPI == 3) {
                float b0 = bias[c0], b1 = bias[c0 + 1];
                v0 += b0; v1 += b1; v2 += b0; v3 += b1;
            }
            if (EPI == 1 || EPI == 3) {
                v0 = fmaxf(v0, 0.f); v1 = fmaxf(v1, 0.f);
                v2 = fmaxf(v2, 0.f); v3 = fmaxf(v3, 0.f);
            }
            if (RND) { v0 = rtf(v0); v1 = rtf(v1); v2 = rtf(v2); v3 = rtf(v3); }
            *(float2*)(C + (size_t)r0 * ldc + c0) = make_float2(v0, v1);
            *(float2*)(C + (size_t)r1 * ldc + c0) = make_float2(v2, v3);
        }
    }
}

// ---------------- branch GEMM kernels ----------------
__global__ void __launch_bounds__(256) k_gemm_node(
    const float* __restrict__ Xm, const float* __restrict__ Wncat, float* __restrict__ XWcat)
{
    __shared__ SmemGemm S;
    int id = blockIdx.x;  // 32
    gemm_dev<0,false>(S, Xm, Wncat, XWcat, 512, 256, 256, (id >> 1) * 128, (id & 1) * 128, nullptr);
}

__global__ void __launch_bounds__(256) k_gemm_edge(
    const float* __restrict__ Eg, const float* __restrict__ WeR, float* __restrict__ EgWe)
{
    __shared__ SmemGemm S;
    gemm_dev<0,false>(S, Eg, WeR, EgWe, 256, 128, 128, blockIdx.x * 128, 0, nullptr);
}

__global__ void __launch_bounds__(256) k_gemm_pair(
    const float* __restrict__ pairE, const float* __restrict__ We2R, float* __restrict__ ci)
{
    __shared__ SmemGemm S;
    // relu(pairE @ We2), tf32-rounded, written straight into ci[:, 384:512]
    gemm_dev<1,true>(S, pairE, We2R, ci + 384, 256, 128, CI, blockIdx.x * 128, 0, nullptr);
}

__global__ void __launch_bounds__(256) k_gemm_heads(
    const float* __restrict__ ci, const float* __restrict__ Wcat,
    const float* __restrict__ bcat, float* __restrict__ hid)
{
    __shared__ SmemGemm S;
    int id = blockIdx.x;  // 384
    gemm_dev<3,false>(S, ci, Wcat, hid, 512, 768, 768, (id / 6) * 128, (id % 6) * 128, bcat);
}

// ---------------- prep kernels (per branch) ----------------
// EDGE branch: Eg gather [0,16384) + WeR [16384,16448) + CSR [16448,16464)
constexpr int PE_EG_END  = Bc * Mc;                        // 16384
constexpr int PE_WE_END  = PE_EG_END + (DEc * WEc) / 512;  // +64
constexpr int PE_TOTAL   = PE_WE_END + Bc;                 // +16

__global__ void __launch_bounds__(128) k_prep_edge(
    const float* __restrict__ ef, const int* __restrict__ eidx, const int* __restrict__ nedg,
    float* __restrict__ Eg, const float* __restrict__ We, float* __restrict__ WeR)
{
    const int blk = blockIdx.x, tid = threadIdx.x;
    if (blk < PE_EG_END) {
        int b = blk >> 10, m = blk & 1023;
        float2 v = make_float2(0.f, 0.f);
        if (m < nedg[b]) {
            int s = eidx[b * 2 * Mc + m];
            int d = eidx[b * 2 * Mc + Mc + m];
            v = ((const float2*)(ef + (((size_t)b * Nc + s) * Nc + d) * DEc))[tid];
            v.x = rtf(v.x); v.y = rtf(v.y);
        }
        ((float2*)(Eg + (size_t)blk * DEc))[tid] = v;
    } else if (blk < PE_WE_END) {
        int idx = (blk - PE_EG_END) * 128 + tid;
        float4 v = ((const float4*)We)[idx];
        v.x = rtf(v.x); v.y = rtf(v.y); v.z = rtf(v.z); v.w = rtf(v.w);
        ((float4*)WeR)[idx] = v;
    } else {
        __shared__ int ssrc[Mc];
        __shared__ int scnt[128];
        int b = blk - PE_WE_END;
        for (int i = tid; i < Mc; i += 128) ssrc[i] = eidx[b * 2 * Mc + i];
        __syncthreads();
        int cnt = 0;
        for (int m = 0; m < Mc; m++) if (ssrc[m] == tid) cnt++;
        scnt[tid] = cnt;
        __syncthreads();
        int off = 0;
        for (int u = 0; u < tid; u++) off += scnt[u];
        d_csr_off[b][tid] = off;
        if (tid == 127) d_csr_off[b][128] = off + cnt;
        int c = off;
        for (int m = 0; m < Mc; m++)
            if (ssrc[m] == tid) d_csr_list[b][c++] = m;
    }
}

// NODE branch: Xm [0,2048) + Wncat [2048,2560) + Wcat/bcat [2560,3584)
constexpr int PN_XM_END = Bc * Nc;                       // 2048
constexpr int PN_WN_END = PN_XM_END + (DNc * WNc) / 128; // +512
constexpr int PN_TOTAL  = PN_WN_END + (CI * HIDc) / 128; // +1024

__global__ void __launch_bounds__(128) k_prep_node(
    const float* __restrict__ nf, const int* __restrict__ nobj, float* __restrict__ Xm,
    const float* __restrict__ Wn, const float* __restrict__ Wn2, float* __restrict__ Wncat,
    const float* __restrict__ lrW1, const float* __restrict__ scrW1, const float* __restrict__ mrW1,
    const float* __restrict__ lrb1, const float* __restrict__ scrb1, const float* __restrict__ mrb1,
    float* __restrict__ Wcat, float* __restrict__ bcat)
{
    const int blk = blockIdx.x, tid = threadIdx.x;
    if (blk < PN_XM_END) {
        int b = blk >> 7, n = blk & 127;
        float4 v = make_float4(0.f, 0.f, 0.f, 0.f);
        if (n < nobj[b]) {
            v = ((const float4*)(nf + (size_t)blk * DNc))[tid];
            v.x = rtf(v.x); v.y = rtf(v.y); v.z = rtf(v.z); v.w = rtf(v.w);
        }
        ((float4*)(Xm + (size_t)blk * DNc))[tid] = v;
    } else if (blk < PN_WN_END) {
        int idx = (blk - PN_XM_END) * 128 + tid;
        int k = idx >> 7, c = idx & 127;
        Wncat[(size_t)k * 256 + c]       = rtf(Wn[idx]);
        Wncat[(size_t)k * 256 + 128 + c] = rtf(Wn2[idx]);
    } else {
        int idx = (blk - PN_WN_END) * 128 + tid;
        int k = idx >> 8, c = idx & 255;
        Wcat[(size_t)k * HID3 + c]             = rtf(lrW1[idx]);
        Wcat[(size_t)k * HID3 + HIDc + c]      = rtf(scrW1[idx]);
        Wcat[(size_t)k * HID3 + 2 * HIDc + c]  = rtf(mrW1[idx]);
        if (blk == PN_WN_END) {
            for (int i = tid; i < HIDc; i += 128) {
                bcat[i]             = lrb1[i];
                bcat[HIDc + i]      = scrb1[i];
                bcat[2 * HIDc + i]  = mrb1[i];
            }
        }
    }
}

// PAIR branch: pairE [0,8192) + We2R [8192,8256)
constexpr int PP_PAIR_END = Bc * Pc;                         // 8192
constexpr int PP_TOTAL    = PP_PAIR_END + (DEc * WEc) / 512; // +64

__global__ void __launch_bounds__(128) k_prep_pair(
    const float* __restrict__ ef, const int* __restrict__ opair, float* __restrict__ pairE,
    const float* __restrict__ We2, float* __restrict__ We2R)
{
    const int blk = blockIdx.x, tid = threadIdx.x;
    if (blk < PP_PAIR_END) {
        int b = blk >> 9, k = blk & 511;
        int p0 = opair[(b * Pc + k) * 2 + 0];
        int p1 = opair[(b * Pc + k) * 2 + 1];
        float2 v = ((const float2*)(ef + (((size_t)b * Nc + p0) * Nc + p1) * DEc))[tid];
        v.x = rtf(v.x); v.y = rtf(v.y);
        ((float2*)(pairE + (size_t)blk * DEc))[tid] = v;
    } else {
        int idx = (blk - PP_PAIR_END) * 128 + tid;
        float4 v = ((const float4*)We2)[idx];
        v.x = rtf(v.x); v.y = rtf(v.y); v.z = rtf(v.z); v.w = rtf(v.w);
        ((float4*)We2R)[idx] = v;
    }
}

// ---------------- sparse adjacency (loops trimmed to cnt) ----------------
__device__ __forceinline__ void adj_dev(
    const float* __restrict__ Adj, const float* __restrict__ Feat,
    const int* __restrict__ cntArr, float* __restrict__ Out,
    int blk, int ROWLEN, int featStride,
    float* srow, int* sidx, float* sval, int* scount)
{
    const int b   = blk / ROWLEN;
    const int i   = blk % ROWLEN;
    const int tid = threadIdx.x;
    const int cnt = cntArr[b];

    float* outRow = Out + (size_t)blk * 128;
    if (i >= cnt) { outRow[tid] = 0.f; return; }

    // stage only the live prefix of the row (j >= cnt is predicated off anyway)
    const float4* A4 = (const float4*)(Adj + ((size_t)b * ROWLEN + i) * ROWLEN);
    float4* s4 = (float4*)srow;
    const int nv4 = (cnt + 3) >> 2;
    for (int j = tid; j < nv4; j += 128) s4[j] = A4[j];
    __syncthreads();

    if (tid < 32) {
        int cn = 0;
        for (int base = 0; base < cnt; base += 32) {
            int j = base + tid;
            float v = (j < cnt) ? srow[j] : 0.f;
            bool nz = (v != 0.f) && (j < cnt);
            unsigned msk = __ballot_sync(0xffffffffu, nz);
            int pos = cn + __popc(msk & ((1u << tid) - 1u));
            if (nz) { sidx[pos] = j; sval[pos] = v; }
            cn += __popc(msk);
        }
        if (tid == 0) *scount = cn;
    }
    __syncthreads();

    const int n = *scount;
    const float* Fb = Feat + (size_t)b * ROWLEN * featStride;
    float acc = Fb[(size_t)i * featStride + tid];     // + eye*mask term
    for (int t = 0; t < n; t++)
        acc = fmaf(sval[t], Fb[(size_t)sidx[t] * featStride + tid], acc);
    outRow[tid] = fmaxf(acc, 0.f);
}

__global__ void __launch_bounds__(128) k_adj_node(
    const float* __restrict__ adjN, const float* __restrict__ XWcat,
    const int* __restrict__ nobj, float* __restrict__ h)
{
    __shared__ float srow[Nc];
    __shared__ int   sidx[Nc];
    __shared__ float sval[Nc];
    __shared__ int   scount;
    adj_dev(adjN, XWcat, nobj, h, blockIdx.x, Nc, 256, srow, sidx, sval, &scount);
}

__global__ void __launch_bounds__(128) k_adj_edge(
    const float* __restrict__ adjM, const float* __restrict__ EgWe,
    const int* __restrict__ nedg, float* __restrict__ g)
{
    __shared__ float srow[Mc];
    __shared__ int   sidx[Mc];
    __shared__ float sval[Mc];
    __shared__ int   scount;
    adj_dev(adjM, EgWe, nedg, g, blockIdx.x, Mc, 128, srow, sidx, sval, &scount);
}

// ---------------- CSR scatter-add agg (once per node, edge branch) ----------------
__global__ void __launch_bounds__(128) k_agg(
    const float* __restrict__ g, float* __restrict__ agg)
{
    int bn = blockIdx.x;
    int b = bn >> 7, n = bn & 127;
    int off = d_csr_off[b][n];
    int end = d_csr_off[b][n + 1];
    const float* gb = g + (size_t)b * Mc * WEc;
    float acc = 0.f;
    for (int t = off; t < end; t++) {
        int m = d_csr_list[b][t];
        acc += gb[(size_t)m * WEc + threadIdx.x];
    }
    agg[(size_t)bn * WEc + threadIdx.x] = acc;
}

// ---------------- build classifier input (cols 0..384) ----------------
__global__ void __launch_bounds__(128) k_build_ci(
    const int* __restrict__ opair, const int* __restrict__ nobj,
    const float* __restrict__ h, const float* __restrict__ agg,
    const float* __restrict__ XWcat, float* __restrict__ ci)
{
    int bk = blockIdx.x;
    int b = bk >> 9, k = bk & 511;
    int p0 = opair[(b * Pc + k) * 2 + 0];
    int p1 = opair[(b * Pc + k) * 2 + 1];
    int no = nobj[b];
    float nm0 = (p0 < no) ? 1.f : 0.f;
    float nm1 = (p1 < no) ? 1.f : 0.f;
    int c = threadIdx.x;
    const float* hb = h    + (size_t)b * Nc * WNc;
    const float* ab = agg  + (size_t)b * Nc * WEc;
    const float* xb = XWcat + (size_t)b * Nc * 256 + 128;   // Xp = cols [128,256)
    float* co = ci + (size_t)bk * CI;
    co[c]       = rtf(hb[(size_t)p0 * WNc + c] + hb[(size_t)p1 * WNc + c]);
    co[128 + c] = rtf(ab[(size_t)p0 * WEc + c] * nm0 + ab[(size_t)p1 * WEc + c] * nm1);
    co[256 + c] = rtf(fmaxf(xb[(size_t)p0 * 256 + c] + xb[(size_t)p1 * 256 + c], 0.f));
}

// ---------------- fused output layers (lr 9 | cr 6 | mr 17) ----------------
__global__ void __launch_bounds__(128) k_heads_out(
    const float* __restrict__ hid,
    const float* __restrict__ lrW2,  const float* __restrict__ lrb2,
    const float* __restrict__ scrW2, const float* __restrict__ scrb2,
    const float* __restrict__ mrW2,  const float* __restrict__ mrb2,
    float* __restrict__ out)
{
    __shared__ float sh[HID3];
    const int row = blockIdx.x, tid = threadIdx.x;
    const float2* hr2 = (const float2*)(hid + (size_t)row * HID3);
    float2* sh2 = (float2*)sh;
    #pragma unroll
    for (int i = 0; i < 3; i++) sh2[i * 128 + tid] = hr2[i * 128 + tid];
    __syncthreads();

    const int o    = tid >> 2;
    const int part = tid & 3;
    const float* W2; const float* b2; int off, OUT, oo; float* dst;
    const size_t rows = (size_t)Bc * Pc;
    if (o < 9)       { W2 = lrW2;  b2 = lrb2;  off = 0;   OUT = 9;  oo = o;      dst = out; }
    else if (o < 15) { W2 = scrW2; b2 = scrb2; off = 256; OUT = 6;  oo = o - 9;  dst = out + rows * 9; }
    else             { W2 = mrW2;  b2 = mrb2;  off = 512; OUT = 17; oo = o - 15; dst = out + rows * 15; }

    float acc = 0.f;
    const int k0 = part * 64;
    #pragma unroll 4
    for (int kk = k0; kk < k0 + 64; kk++)
        acc += sh[off + kk] * W2[kk * OUT + oo];
    acc += __shfl_xor_sync(0xffffffffu, acc, 1);
    acc += __shfl_xor_sync(0xffffffffu, acc, 2);
    if (part == 0) dst[(size_t)row * OUT + oo] = acc + b2[oo];
}

// ---------------- launch (3 parallel stream branches, fork/join) ----------------
extern "C" void kernel_launch(void* const* d_in, const int* in_sizes, int n_in,
                              void* d_out, int out_size)
{
    const float* nf    = (const float*)d_in[0];
    const float* ef    = (const float*)d_in[1];
    const float* adj   = (const float*)d_in[2];
    const float* ladj  = (const float*)d_in[3];
    const int*   eidx  = (const int*)d_in[4];
    const int*   opair = (const int*)d_in[5];
    const int*   nobj  = (const int*)d_in[6];
    const int*   nedg  = (const int*)d_in[7];
    const float* Wn    = (const float*)d_in[8];
    const float* We    = (const float*)d_in[9];
    const float* Wn2   = (const float*)d_in[10];
    const float* We2   = (const float*)d_in[11];
    const float* scrW1 = (const float*)d_in[12];
    const float* scrb1 = (const float*)d_in[13];
    const float* scrW2 = (const float*)d_in[14];
    const float* scrb2 = (const float*)d_in[15];
    const float* lrW1  = (const float*)d_in[16];
    const float* lrb1  = (const float*)d_in[17];
    const float* lrW2  = (const float*)d_in[18];
    const float* lrb2  = (const float*)d_in[19];
    const float* mrW1  = (const float*)d_in[20];
    const float* mrb1  = (const float*)d_in[21];
    const float* mrW2  = (const float*)d_in[22];
    const float* mrb2  = (const float*)d_in[23];
    float* out = (float*)d_out;

    float* S = nullptr;
    cudaGetSymbolAddress((void**)&S, d_scratch);
    float* Xm    = S + OFF_XM;
    float* XWcat = S + OFF_XWCAT;
    float* h     = S + OFF_H;
    float* Eg    = S + OFF_EG;
    float* EgWe  = S + OFF_EGWE;
    float* g     = S + OFF_G;
    float* agg   = S + OFF_AGG;
    float* pairE = S + OFF_PAIRE;
    float* ci    = S + OFF_CI;
    float* hid   = S + OFF_HID;
    float* Wncat = S + OFF_WNCAT;
    float* Wcat  = S + OFF_WCAT;
    float* bcat  = S + OFF_BCAT;
    float* WeR   = S + OFF_WER;
    float* We2R  = S + OFF_WE2R;

    cudaStream_t s1, s2;
    cudaStreamCreateWithFlags(&s1, cudaStreamNonBlocking);
    cudaStreamCreateWithFlags(&s2, cudaStreamNonBlocking);
    cudaEvent_t eF, eN, eP;
    cudaEventCreateWithFlags(&eF, cudaEventDisableTiming);
    cudaEventCreateWithFlags(&eN, cudaEventDisableTiming);
    cudaEventCreateWithFlags(&eP, cudaEventDisableTiming);

    // fork
    cudaEventRecord(eF, 0);
    cudaStreamWaitEvent(s1, eF, 0);
    cudaStreamWaitEvent(s2, eF, 0);

    // NODE branch (s1): Xm mask + weight packs -> X@[Wn|Wn2] -> node adjacency
    k_prep_node<<<PN_TOTAL, 128, 0, s1>>>(nf, nobj, Xm, Wn, Wn2, Wncat,
                                          lrW1, scrW1, mrW1, lrb1, scrb1, mrb1, Wcat, bcat);
    k_gemm_node<<<32, 256, 0, s1>>>(Xm, Wncat, XWcat);
    k_adj_node<<<Bc * Nc, 128, 0, s1>>>(adj, XWcat, nobj, h);
    cudaEventRecord(eN, s1);

    // PAIR branch (s2): pairE gather -> relu(pairE@We2) -> ci[:,384:]
    k_prep_pair<<<PP_TOTAL, 128, 0, s2>>>(ef, opair, pairE, We2, We2R);
    k_gemm_pair<<<64, 256, 0, s2>>>(pairE, We2R, ci);
    cudaEventRecord(eP, s2);

    // EDGE branch (origin): Eg gather + CSR -> Eg@We -> line adjacency -> agg
    k_prep_edge<<<PE_TOTAL, 128>>>(ef, eidx, nedg, Eg, We, WeR);
    k_gemm_edge<<<128, 256>>>(Eg, WeR, EgWe);
    k_adj_edge<<<Bc * Mc, 128>>>(ladj, EgWe, nedg, g);
    k_agg<<<Bc * Nc, 128>>>(g, agg);

    // join
    cudaStreamWaitEvent(0, eN, 0);
    cudaStreamWaitEvent(0, eP, 0);

    // tail: ci cols 0..384, heads GEMM, output layers
    k_build_ci<<<Bc * Pc, 128>>>(opair, nobj, h, agg, XWcat, ci);
    k_gemm_heads<<<(Bc * Pc / 128) * 6, 256>>>(ci, Wcat, bcat, hid);
    k_heads_out<<<Bc * Pc, 128>>>(hid, lrW2, lrb2, scrW2, scrb2, mrW2, mrb2, out);

    cudaEventDestroy(eF);
    cudaEventDestroy(eN);
    cudaEventDestroy(eP);
    cudaStreamDestroy(s1);
    cudaStreamDestroy(s2);
}